// round 5
// baseline (speedup 1.0000x reference)
#include <cuda_runtime.h>
#include <cuda_bf16.h>
#include <float.h>

#define Bn 128
#define On 1024
#define In 1024
#define EPSc 1e-7f
#define L2E 1.4426950408889634f

// Scratch (no allocs allowed)
__device__ float  g_c2_om[On * In];   // C^2, o-major  [o][i]
__device__ float  g_c2_im[In * On];   // C^2, i-major  [i][o]
__device__ float2 g_col[Bn * In];     // per (b,i): {copysign(g2, d), Bout}

__device__ __forceinline__ float rsqrt_nr(float x) {
    float r;
    asm("rsqrt.approx.ftz.f32 %0, %1;" : "=f"(r) : "f"(x));
    // one Newton step: r *= (1.5 - 0.5*x*r*r)
    float t = x * r;
    r = r * fmaf(t * r, -0.5f, 1.5f);
    return r;
}

__device__ __forceinline__ float ex2(float x) {
    float r;
    asm("ex2.approx.ftz.f32 %0, %1;" : "=f"(r) : "f"(x));
    return r;
}

// ---------------- Kernel P: C^2 in both layouts ----------------
__global__ void kprep(const float* __restrict__ ix, const float* __restrict__ iy,
                      const float* __restrict__ ox, const float* __restrict__ oy,
                      const float* __restrict__ la, const float* __restrict__ lm) {
    int idx = blockIdx.x * blockDim.x + threadIdx.x;
    if (idx >= On * In) return;
    float c = (ix[idx] / iy[idx] + la[idx]) * (1.0f + lm[idx]) - ox[idx] / oy[idx];
    float c2 = c * c;
    int o = idx >> 10;
    int i = idx & 1023;
    g_c2_om[idx] = c2;
    g_c2_im[i * On + o] = c2;
}

// ---------------- Kernel A: per-(b,i) softmax denominator ----------------
// grid = I blocks, 128 threads (one per b). Column C^2[:,i] staged in SMEM.
__global__ void kcol(const float* __restrict__ data) {
    __shared__ float4 sc2[On / 4];
    __shared__ float  smin[4];
    int i = blockIdx.x;
    int t = threadIdx.x;  // = b

    const float4* src = (const float4*)(g_c2_im + i * On);
    float mn = FLT_MAX;
#pragma unroll
    for (int k = 0; k < 2; k++) {
        float4 v = src[t + 128 * k];
        sc2[t + 128 * k] = v;
        mn = fminf(mn, fminf(fminf(v.x, v.y), fminf(v.z, v.w)));
    }
#pragma unroll
    for (int s = 16; s; s >>= 1) mn = fminf(mn, __shfl_xor_sync(0xffffffffu, mn, s));
    if ((t & 31) == 0) smin[t >> 5] = mn;
    __syncthreads();
    float m2 = fminf(fminf(smin[0], smin[1]), fminf(smin[2], smin[3]));

    int b = t;
    float d = data[b * In + i];
    float g = 1.0f / (1.0f + __expf(-d));
    float g2 = g * g;
    float smax = rsqrt_nr(fmaf(m2, g2, EPSc));
    float Bm = -smax * L2E;

    float S0 = 0.f, S1 = 0.f, S2 = 0.f, S3 = 0.f;
#pragma unroll 4
    for (int o4 = 0; o4 < On / 4; o4++) {
        float4 c = sc2[o4];
        S0 += ex2(fmaf(rsqrt_nr(fmaf(c.x, g2, EPSc)), L2E, Bm));
        S1 += ex2(fmaf(rsqrt_nr(fmaf(c.y, g2, EPSc)), L2E, Bm));
        S2 += ex2(fmaf(rsqrt_nr(fmaf(c.z, g2, EPSc)), L2E, Bm));
        S3 += ex2(fmaf(rsqrt_nr(fmaf(c.w, g2, EPSc)), L2E, Bm));
    }
    float S = (S0 + S1) + (S2 + S3);

    // Fold d/S into the exponent: Bout = Bm + log2|d| - log2(S); sign kept in g2s.
    float Bout = Bm + __log2f(fabsf(d)) - __log2f(S);
    g_col[b * In + i] = make_float2(copysignf(g2, d), Bout);
}

// ---------------- Kernel B: out[b,o] = sum_i sign * exp2(r*L2E + Bout) ----------------
// grid = (16 i-chunks of 64, 32 b-groups of 4). 256 threads; each thread owns
// 4 o-rows (t, t+256, t+512, t+768) x 4 b's. C^2 values reused across 4 b's
// in registers -> L2 traffic = 4MB * 32 = 128MB total.
__global__ void kout(float* __restrict__ out) {
    __shared__ float2 scol[4][64];
    int t = threadIdx.x;
    int bbase = blockIdx.y * 4;
    int ibase = blockIdx.x * 64;

    {
        int bb = t >> 6, ii = t & 63;
        scol[bb][ii] = g_col[(bbase + bb) * In + ibase + ii];
    }
    __syncthreads();

    float acc[4][4];
#pragma unroll
    for (int oo = 0; oo < 4; oo++)
#pragma unroll
        for (int bb = 0; bb < 4; bb++) acc[oo][bb] = 0.f;

    int o0 = t;
#pragma unroll 1
    for (int i4 = 0; i4 < 16; i4++) {
        int i = ibase + i4 * 4;
        float4 c2v[4];
#pragma unroll
        for (int oo = 0; oo < 4; oo++)
            c2v[oo] = *(const float4*)(g_c2_om + (o0 + oo * 256) * In + i);

#pragma unroll
        for (int ii = 0; ii < 4; ii++) {
            float g2[4], Bb[4], sg[4];
#pragma unroll
            for (int bb = 0; bb < 4; bb++) {
                float2 cv = scol[bb][i4 * 4 + ii];
                g2[bb] = fabsf(cv.x);
                sg[bb] = copysignf(1.0f, cv.x);
                Bb[bb] = cv.y;
            }
#pragma unroll
            for (int oo = 0; oo < 4; oo++) {
                float c2 = ((const float*)&c2v[oo])[ii];
#pragma unroll
                for (int bb = 0; bb < 4; bb++) {
                    float x = fmaf(c2, g2[bb], EPSc);
                    float r = rsqrt_nr(x);
                    float e = ex2(fmaf(r, L2E, Bb[bb]));
                    acc[oo][bb] = fmaf(e, sg[bb], acc[oo][bb]);
                }
            }
        }
    }

#pragma unroll
    for (int oo = 0; oo < 4; oo++)
#pragma unroll
        for (int bb = 0; bb < 4; bb++)
            atomicAdd(&out[(bbase + bb) * On + (o0 + oo * 256)], acc[oo][bb]);
}

extern "C" void kernel_launch(void* const* d_in, const int* in_sizes, int n_in,
                              void* d_out, int out_size) {
    const float* data = (const float*)d_in[0];
    const float* ix   = (const float*)d_in[1];
    const float* iy   = (const float*)d_in[2];
    const float* ox   = (const float*)d_in[3];
    const float* oy   = (const float*)d_in[4];
    const float* la   = (const float*)d_in[5];
    const float* lm   = (const float*)d_in[6];
    float* out = (float*)d_out;

    cudaMemsetAsync(out, 0, (size_t)out_size * sizeof(float));

    kprep<<<(On * In + 255) / 256, 256>>>(ix, iy, ox, oy, la, lm);
    kcol<<<In, 128>>>(data);
    kout<<<dim3(16, 32), 256>>>(out);
}

// round 6
// speedup vs baseline: 1.1267x; 1.1267x over previous
#include <cuda_runtime.h>
#include <cuda_bf16.h>
#include <float.h>

#define Bn 128
#define On 1024
#define In 1024
#define EPSc 1e-7f
#define L2E 1.4426950408889634f

#define IB 2    // i's per barrier round
#define GB 4    // b's per block
#define OC 4    // o's per thread
#define ICK 64  // i's per block

// Scratch (no allocs allowed)
__device__ float    g_c2_im[In * On];   // C^2, i-major [i][o]
__device__ unsigned g_min[In];          // min over o of C^2[:,i] (uint-ordered, all >=0)
__device__ float2   g_bi[Bn * In];      // per (b,i): {g^2, Bm = -smax*L2E}

__device__ __forceinline__ float rsqrt_nr(float x) {
    float r;
    asm("rsqrt.approx.ftz.f32 %0, %1;" : "=f"(r) : "f"(x));
    float t = x * r;
    return r * fmaf(t * r, -0.5f, 1.5f);   // one Newton step
}

__device__ __forceinline__ float ex2(float x) {
    float r;
    asm("ex2.approx.ftz.f32 %0, %1;" : "=f"(r) : "f"(x));
    return r;
}

// ---------------- init per-i min to +inf ----------------
__global__ void kinit() {
    int i = blockIdx.x * 256 + threadIdx.x;
    if (i < In) g_min[i] = 0x7F800000u;
}

// ---------------- Kernel P: C^2 transpose (o-major inputs -> i-major) + per-i min ----
// 32x32 tiles, coalesced both ways; warp-min + atomicMin for g_min.
__global__ void kprep(const float* __restrict__ ix, const float* __restrict__ iy,
                      const float* __restrict__ ox, const float* __restrict__ oy,
                      const float* __restrict__ la, const float* __restrict__ lm) {
    __shared__ float tile[32][33];
    int tx = threadIdx.x & 31;
    int ty = threadIdx.x >> 5;
    int ob  = (blockIdx.x & 31) * 32;   // o tile base
    int ibt = (blockIdx.x >> 5) * 32;   // i tile base

#pragma unroll
    for (int k = 0; k < 4; k++) {
        int o = ob + ty + k * 8;
        int idx = o * In + ibt + tx;    // coalesced over tx (consecutive i)
        float c = (ix[idx] / iy[idx] + la[idx]) * (1.0f + lm[idx]) - ox[idx] / oy[idx];
        tile[ty + k * 8][tx] = c * c;
    }
    __syncthreads();

#pragma unroll
    for (int k = 0; k < 4; k++) {
        int il = ty + k * 8;            // local i (fixed per warp per k)
        float v = tile[tx][il];         // stride-33 -> conflict-free
        g_c2_im[(ibt + il) * In + ob + tx] = v;   // coalesced over tx (consecutive o)
        float mn = v;
#pragma unroll
        for (int s = 16; s; s >>= 1) mn = fminf(mn, __shfl_xor_sync(0xffffffffu, mn, s));
        if (tx == 0) atomicMin(&g_min[ibt + il], __float_as_uint(mn));
    }
}

// ---------------- Kernel G: per-(b,i) scalars {g^2, Bm} ----------------
__global__ void kg(const float* __restrict__ data) {
    int idx = blockIdx.x * 256 + threadIdx.x;   // b*In + i, contiguous
    int i = idx & (In - 1);
    float d = data[idx];
    float g = 1.0f / (1.0f + __expf(-d));
    float g2 = g * g;
    float m2 = __uint_as_float(g_min[i]);
    float smax = rsqrt_nr(fmaf(m2, g2, EPSc));
    g_bi[idx] = make_float2(g2, -smax * L2E);
}

// ---------------- Kernel F: fused — each softmax term computed ONCE ----------------
// grid = (In/ICK i-chunks, Bn/GB b-groups), 256 threads.
// Thread owns o in {t, t+256, t+512, t+768} x 4 b's; per round of IB i's:
//   compute e (kept in regs), block-reduce S per (b,i), acc += e * (d/S).
__global__ void __launch_bounds__(256, 2) kfused(const float* __restrict__ data,
                                                 float* __restrict__ out) {
    __shared__ float  sc2[IB * In];       // 8KB: IB C^2 rows (contiguous in gmem)
    __shared__ float2 sbi[IB][GB];        // {g2, Bm}
    __shared__ float  sd[IB][GB];         // d
    __shared__ float  sred[8][IB * GB];   // per-warp partial sums
    __shared__ float  scoef[IB][GB];      // d / S

    int t = threadIdx.x;
    int warp = t >> 5, lane = t & 31;
    int ibase = blockIdx.x * ICK;
    int bbase = blockIdx.y * GB;

    float acc[GB][OC];
#pragma unroll
    for (int bb = 0; bb < GB; bb++)
#pragma unroll
        for (int oo = 0; oo < OC; oo++) acc[bb][oo] = 0.f;

    for (int i0 = 0; i0 < ICK; i0 += IB) {
        int ig = ibase + i0;
        {   // IB consecutive rows = IB*In contiguous floats
            const float4* src = (const float4*)(g_c2_im + (size_t)ig * In);
            float4* dst = (float4*)sc2;
            dst[t]       = src[t];
            dst[t + 256] = src[t + 256];
        }
        if (t < IB * GB) {
            int ii = t >> 2, bb = t & 3;
            int off = (bbase + bb) * In + ig + ii;
            sbi[ii][bb] = g_bi[off];
            sd[ii][bb]  = data[off];
        }
        __syncthreads();

        float e[IB][GB][OC];
        float psum[IB][GB];
#pragma unroll
        for (int ii = 0; ii < IB; ii++) {
            float c2v[OC];
#pragma unroll
            for (int oo = 0; oo < OC; oo++) c2v[oo] = sc2[ii * In + t + oo * 256];
#pragma unroll
            for (int bb = 0; bb < GB; bb++) {
                float g2 = sbi[ii][bb].x;
                float Bm = sbi[ii][bb].y;
                float p = 0.f;
#pragma unroll
                for (int oo = 0; oo < OC; oo++) {
                    float x = fmaf(c2v[oo], g2, EPSc);
                    float r = rsqrt_nr(x);
                    float ev = ex2(fmaf(r, L2E, Bm));
                    e[ii][bb][oo] = ev;
                    p += ev;
                }
                psum[ii][bb] = p;
            }
        }

        // reduce S[b,i] across block
#pragma unroll
        for (int ii = 0; ii < IB; ii++)
#pragma unroll
            for (int bb = 0; bb < GB; bb++) {
                float p = psum[ii][bb];
#pragma unroll
                for (int s = 16; s; s >>= 1) p += __shfl_xor_sync(0xffffffffu, p, s);
                if (lane == 0) sred[warp][ii * GB + bb] = p;
            }
        __syncthreads();
        if (t < IB * GB) {
            int ii = t >> 2, bb = t & 3;
            float S = 0.f;
#pragma unroll
            for (int w = 0; w < 8; w++) S += sred[w][t];
            scoef[ii][bb] = __fdividef(sd[ii][bb], S);
        }
        __syncthreads();

#pragma unroll
        for (int ii = 0; ii < IB; ii++)
#pragma unroll
            for (int bb = 0; bb < GB; bb++) {
                float coef = scoef[ii][bb];
#pragma unroll
                for (int oo = 0; oo < OC; oo++)
                    acc[bb][oo] = fmaf(e[ii][bb][oo], coef, acc[bb][oo]);
            }
        __syncthreads();
    }

#pragma unroll
    for (int bb = 0; bb < GB; bb++)
#pragma unroll
        for (int oo = 0; oo < OC; oo++)
            atomicAdd(&out[(bbase + bb) * On + t + oo * 256], acc[bb][oo]);
}

extern "C" void kernel_launch(void* const* d_in, const int* in_sizes, int n_in,
                              void* d_out, int out_size) {
    const float* data = (const float*)d_in[0];
    const float* ix   = (const float*)d_in[1];
    const float* iy   = (const float*)d_in[2];
    const float* ox   = (const float*)d_in[3];
    const float* oy   = (const float*)d_in[4];
    const float* la   = (const float*)d_in[5];
    const float* lm   = (const float*)d_in[6];
    float* out = (float*)d_out;

    cudaMemsetAsync(out, 0, (size_t)out_size * sizeof(float));
    kinit<<<4, 256>>>();
    kprep<<<1024, 256>>>(ix, iy, ox, oy, la, lm);
    kg<<<(Bn * In) / 256, 256>>>(data);
    kfused<<<dim3(In / ICK, Bn / GB), 256>>>(data, out);
}